// round 11
// baseline (speedup 1.0000x reference)
#include <cuda_runtime.h>
#include <cuda_fp16.h>
#include <math.h>
#include <stdint.h>

// Problem constants
#define BB  64
#define LSQ 512
#define LTK 256
#define DD  256
#define HH  8
#define DHH 32
#define LN_EPS  1e-5f
#define ATT_EPS 1e-6f

// ---------------------------------------------------------------------------
// Scratch (device globals)
// ---------------------------------------------------------------------------
__device__ __align__(16) __half g_Qh  [BB*LSQ*DD];
__device__ __align__(16) __half g_Kh  [BB*LTK*DD];
__device__ __align__(16) __half g_Vh  [BB*LTK*DD];
__device__ float  g_Ksum[BB*HH*DHH];
__device__ __align__(16) __half g_qz  [BB*LSQ*DD];      // Q * z
__device__ __align__(16) __half g_kvwt[BB*DD*DD];       // per-b [n][k] = KVW
__device__ __align__(16) __half g_msgm[BB*LSQ*DD];
__device__ __align__(16) __half g_y   [BB*LSQ*DD];      // ln1 output
__device__ __align__(16) __half g_mh  [BB*LSQ*2*DD];
__device__ __align__(16) __half g_m2h [BB*LSQ*DD];
// weights, transposed to [N, K] in half
__device__ __align__(16) __half g_wkvt  [2*DD*DD];      // [wk ; wv]
__device__ __align__(16) __half g_wmt   [DD*DD];
__device__ __align__(16) __half g_w1t   [2*DD*2*DD];
__device__ __align__(16) __half g_w2t   [DD*2*DD];
__device__ __align__(16) __half g_qcombt[DD*2*DD];      // [Wpq ; wq] as [N=256][K=512]
__device__ float g_bq[DD];                               // pos_b2 @ wq

// ---------------------------------------------------------------------------
// helpers
// ---------------------------------------------------------------------------
__device__ __forceinline__ uint32_t smem_u32(const void* p) {
    uint32_t a;
    asm("{ .reg .u64 t; cvta.to.shared.u64 t, %1; cvt.u32.u64 %0, t; }"
        : "=r"(a) : "l"(p));
    return a;
}

__device__ __forceinline__ void cp_async16(uint32_t saddr, const void* gaddr) {
    asm volatile("cp.async.cg.shared.global [%0], [%1], 16;"
                 :: "r"(saddr), "l"(gaddr));
}
#define CP_COMMIT() asm volatile("cp.async.commit_group;" ::: "memory")
#define CP_WAIT(n)  asm volatile("cp.async.wait_group %0;" :: "n"(n) : "memory")

__device__ __forceinline__ void ldmx4(uint32_t r[4], uint32_t addr) {
    asm volatile("ldmatrix.sync.aligned.m8n8.x4.shared.b16 {%0,%1,%2,%3}, [%4];"
        : "=r"(r[0]), "=r"(r[1]), "=r"(r[2]), "=r"(r[3]) : "r"(addr));
}

__device__ __forceinline__ void mma16816(float d[4], const uint32_t a[4],
                                         uint32_t b0, uint32_t b1) {
    asm volatile(
        "mma.sync.aligned.m16n8k16.row.col.f32.f16.f16.f32 "
        "{%0,%1,%2,%3}, {%4,%5,%6,%7}, {%8,%9}, {%0,%1,%2,%3};"
        : "+f"(d[0]), "+f"(d[1]), "+f"(d[2]), "+f"(d[3])
        : "r"(a[0]), "r"(a[1]), "r"(a[2]), "r"(a[3]), "r"(b0), "r"(b1));
}

__device__ __forceinline__ void sts_h8(uint32_t addr, const __half2 h[4]) {
    asm volatile("st.shared.v4.b32 [%0], {%1,%2,%3,%4};"
        :: "r"(addr),
           "r"(*(const uint32_t*)&h[0]), "r"(*(const uint32_t*)&h[1]),
           "r"(*(const uint32_t*)&h[2]), "r"(*(const uint32_t*)&h[3])
        : "memory");
}

// ---------------------------------------------------------------------------
// fp16 GEMM, cp.async 3-stage, block 128x128x64, 8 warps (2x4), warp 64x32
// AMODE: 0 = half A [*,K]
//        2 = fused-Q: kcol<256 -> relu(coors@w1+b1) computed inline;
//            kcol>=256 -> F fp32 [*,256] converted
//        3 = F fp32 [*,K] converted
//        4 = kcol<256 -> F fp32 [*,256] converted; kcol>=256 -> A half [*,256]
// BATB: Bt += (m0>>9) * 65536 (per-batch B matrix)
// ---------------------------------------------------------------------------
enum { EPI_NONE = 0, EPI_ELU1B = 1, EPI_RELU = 3, EPI_KV = 4 };

#define ROWB 144
#define TILEB (128 * ROWB)             // 18432
#define STAGEB (2 * TILEB)             // 36864
#define NSTAGE 3
#define HG_SMEM (NSTAGE * STAGEB)      // 110592

template<int EPI, int HOUT, int AMODE, int BATB>
__global__ void __launch_bounds__(256)
hgemm(const __half* __restrict__ A,
      const float* __restrict__ F,
      const __half* __restrict__ Bt,
      void* __restrict__ Cv, void* __restrict__ C2,
      int M, int N, int K,
      const float* __restrict__ bias,
      const float* __restrict__ coors, const float* __restrict__ w1p,
      const float* __restrict__ b1p)
{
    extern __shared__ __align__(16) char smem[];
    const uint32_t sb = smem_u32(smem);
    const int tid = threadIdx.x, lane = tid & 31, wid = tid >> 5;
    const int wm = (wid & 1) * 64, wn = (wid >> 1) * 32;
    const int m0 = blockIdx.y * 128, n0 = blockIdx.x * 128;
    const int nk = K >> 6;
    const __half* Btb = BATB ? (Bt + (size_t)(m0 >> 9) * (DD * DD)) : Bt;

    float acc[4][4][4];
    #pragma unroll
    for (int a = 0; a < 4; a++)
        #pragma unroll
        for (int b = 0; b < 4; b++)
            #pragma unroll
            for (int c = 0; c < 4; c++) acc[a][b][c] = 0.f;

    auto issue_stage = [&](int s, int ktile) {
        const uint32_t abase = sb + s * STAGEB;
        const uint32_t bbase = abase + TILEB;
        #pragma unroll
        for (int i = 0; i < 4; i++) {
            const int idx = tid + i * 256;            // 0..1023
            const int row = idx >> 3, c8 = idx & 7;
            const int kcol = ktile * 64 + c8 * 8;
            const uint32_t sad = abase + row * ROWB + c8 * 16;
            if (AMODE == 2) {
                if (kcol < 256) {
                    const int m = m0 + row;
                    const float c0 = coors[m*3+0], c1 = coors[m*3+1],
                                c2 = coors[m*3+2];
                    __half2 h[4];
                    #pragma unroll
                    for (int q = 0; q < 4; q++) {
                        const int n = kcol + 2 * q;
                        float x0 = b1p[n]   + c0*w1p[n]   + c1*w1p[256+n]
                                 + c2*w1p[512+n];
                        float x1 = b1p[n+1] + c0*w1p[n+1] + c1*w1p[256+n+1]
                                 + c2*w1p[512+n+1];
                        h[q] = __floats2half2_rn(fmaxf(x0, 0.f), fmaxf(x1, 0.f));
                    }
                    sts_h8(sad, h);
                } else {
                    const float* fp = F + (size_t)(m0 + row) * 256 + (kcol - 256);
                    const float4 f0 = *(const float4*)fp;
                    const float4 f1 = *(const float4*)(fp + 4);
                    __half2 h[4] = { __floats2half2_rn(f0.x, f0.y),
                                     __floats2half2_rn(f0.z, f0.w),
                                     __floats2half2_rn(f1.x, f1.y),
                                     __floats2half2_rn(f1.z, f1.w) };
                    sts_h8(sad, h);
                }
            } else if (AMODE == 3) {
                const float* fp = F + (size_t)(m0 + row) * K + kcol;
                const float4 f0 = *(const float4*)fp;
                const float4 f1 = *(const float4*)(fp + 4);
                __half2 h[4] = { __floats2half2_rn(f0.x, f0.y),
                                 __floats2half2_rn(f0.z, f0.w),
                                 __floats2half2_rn(f1.x, f1.y),
                                 __floats2half2_rn(f1.z, f1.w) };
                sts_h8(sad, h);
            } else if (AMODE == 4) {
                if (kcol < 256) {
                    const float* fp = F + (size_t)(m0 + row) * 256 + kcol;
                    const float4 f0 = *(const float4*)fp;
                    const float4 f1 = *(const float4*)(fp + 4);
                    __half2 h[4] = { __floats2half2_rn(f0.x, f0.y),
                                     __floats2half2_rn(f0.z, f0.w),
                                     __floats2half2_rn(f1.x, f1.y),
                                     __floats2half2_rn(f1.z, f1.w) };
                    sts_h8(sad, h);
                } else {
                    cp_async16(sad, A + (size_t)(m0 + row) * 256 + (kcol - 256));
                }
            } else {
                cp_async16(sad, A + (size_t)(m0 + row) * K + kcol);
            }
            cp_async16(bbase + row * ROWB + c8 * 16,
                       Btb + (size_t)(n0 + row) * K + kcol);
        }
        CP_COMMIT();
    };

    #pragma unroll
    for (int s = 0; s < NSTAGE - 1; s++) issue_stage(s, s);

    const int lr = lane & 15, lc = (lane >> 4) * 8;

    for (int kt = 0; kt < nk; kt++) {
        CP_WAIT(NSTAGE - 2);
        __syncthreads();
        const int st = kt % NSTAGE;
        if (kt + NSTAGE - 1 < nk)
            issue_stage((kt + NSTAGE - 1) % NSTAGE, kt + NSTAGE - 1);

        const uint32_t abuf = sb + st * STAGEB;
        const uint32_t bbuf = abuf + TILEB;
        #pragma unroll
        for (int ks = 0; ks < 4; ks++) {
            uint32_t afr[4][4], bfr[2][4];
            #pragma unroll
            for (int mi = 0; mi < 4; mi++)
                ldmx4(afr[mi], abuf + (wm + mi * 16 + lr) * ROWB + (ks * 16 + lc) * 2);
            #pragma unroll
            for (int nj = 0; nj < 2; nj++)
                ldmx4(bfr[nj], bbuf + (wn + nj * 16 + lr) * ROWB + (ks * 16 + lc) * 2);
            #pragma unroll
            for (int mi = 0; mi < 4; mi++)
                #pragma unroll
                for (int ni = 0; ni < 4; ni++) {
                    const int nj = ni >> 1;
                    const uint32_t b0 = (ni & 1) ? bfr[nj][1] : bfr[nj][0];
                    const uint32_t b1 = (ni & 1) ? bfr[nj][3] : bfr[nj][2];
                    mma16816(acc[mi][ni], afr[mi], b0, b1);
                }
        }
    }

    // epilogue
    #pragma unroll
    for (int mi = 0; mi < 4; mi++) {
        #pragma unroll
        for (int ni = 0; ni < 4; ni++) {
            const int col = n0 + wn + ni * 8 + (lane & 3) * 2;
            #pragma unroll
            for (int half_m = 0; half_m < 2; half_m++) {
                const int m = m0 + wm + mi * 16 + (lane >> 2) + half_m * 8;
                float v0 = acc[mi][ni][half_m * 2 + 0];
                float v1 = acc[mi][ni][half_m * 2 + 1];
                if (EPI == EPI_ELU1B) {
                    v0 += bias[col];
                    v1 += bias[col + 1];
                    v0 = v0 > 0.f ? v0 + 1.f : expf(v0);
                    v1 = v1 > 0.f ? v1 + 1.f : expf(v1);
                } else if (EPI == EPI_RELU) {
                    v0 = fmaxf(v0, 0.f);
                    v1 = fmaxf(v1, 0.f);
                }
                if (EPI == EPI_KV) {
                    if (col < 256) {
                        v0 = v0 > 0.f ? v0 + 1.f : expf(v0);
                        v1 = v1 > 0.f ? v1 + 1.f : expf(v1);
                        *(__half2*)((__half*)Cv + (size_t)m * 256 + col) =
                            __floats2half2_rn(v0, v1);
                    } else {
                        *(__half2*)((__half*)C2 + (size_t)m * 256 + (col - 256)) =
                            __floats2half2_rn(v0, v1);
                    }
                } else if (HOUT) {
                    *(__half2*)((__half*)Cv + (size_t)m * N + col) = __floats2half2_rn(v0, v1);
                } else {
                    *(float2*)((float*)Cv + (size_t)m * N + col) = make_float2(v0, v1);
                }
            }
        }
    }
}

// ---------------------------------------------------------------------------
// batched weight transpose -> half (into [N][K] layouts)
// ---------------------------------------------------------------------------
__global__ void transpose_all(const float* __restrict__ wk, const float* __restrict__ wv,
                              const float* __restrict__ wm, const float* __restrict__ w1,
                              const float* __restrict__ w2, const float* __restrict__ wq,
                              __half* __restrict__ wkvt, __half* __restrict__ wmt,
                              __half* __restrict__ w1t, __half* __restrict__ w2t,
                              __half* __restrict__ qcombt)
{
    __shared__ float t[32][33];
    const int z = blockIdx.z;
    const float* W; __half* Wt; int Kd, Nd, Ks_out, roff = 0, coff = 0;
    switch (z) {
        case 0: W = wk; Wt = wkvt;  Kd = 256; Nd = 256; Ks_out = 256; break;
        case 1: W = wv; Wt = wkvt;  Kd = 256; Nd = 256; Ks_out = 256; roff = 256; break;
        case 2: W = wm; Wt = wmt;   Kd = 256; Nd = 256; Ks_out = 256; break;
        case 3: W = w1; Wt = w1t;   Kd = 512; Nd = 512; Ks_out = 512; break;
        case 4: W = w2; Wt = w2t;   Kd = 512; Nd = 256; Ks_out = 512; break;
        default: W = wq; Wt = qcombt; Kd = 256; Nd = 256; Ks_out = 512; coff = 256; break;
    }
    const int k0 = blockIdx.y * 32, n0 = blockIdx.x * 32;
    if (k0 >= Kd || n0 >= Nd) return;
    t[threadIdx.y][threadIdx.x] = W[(size_t)(k0 + threadIdx.y) * Nd + n0 + threadIdx.x];
    __syncthreads();
    Wt[(size_t)(roff + n0 + threadIdx.y) * Ks_out + coff + k0 + threadIdx.x] =
        __float2half(t[threadIdx.x][threadIdx.y]);
}

// Wpq[k][n] = (posw2 @ wq)[k][n] -> qcombt[n][k] (k < 256)
__global__ void __launch_bounds__(256)
wpq_kernel(const float* __restrict__ posw2, const float* __restrict__ wq,
           __half* __restrict__ qcombt)
{
    __shared__ float srow[256];
    const int k = blockIdx.x, n = threadIdx.x;
    srow[n] = posw2[(size_t)k * 256 + n];
    __syncthreads();
    float acc = 0.f;
    #pragma unroll 8
    for (int j = 0; j < 256; j++)
        acc = fmaf(srow[j], wq[(size_t)j * 256 + n], acc);
    qcombt[(size_t)n * 512 + k] = __float2half(acc);
}

// bq[n] = (pos_b2 @ wq)[n]
__global__ void __launch_bounds__(256)
bq_kernel(const float* __restrict__ pb2, const float* __restrict__ wq,
          float* __restrict__ bq)
{
    const int n = threadIdx.x;
    float acc = 0.f;
    for (int j = 0; j < 256; j++)
        acc = fmaf(pb2[j], wq[(size_t)j * 256 + n], acc);
    bq[n] = acc;
}

// ---------------------------------------------------------------------------
// KV reduce + KVW = KV @ Wm_h, per (b,h); writes Ksum and kvwt[b][n][h*32+d]
// ---------------------------------------------------------------------------
__global__ void __launch_bounds__(1024)
kv_kvw_kernel(const __half* __restrict__ Kf, const __half* __restrict__ Vf,
              const __half* __restrict__ wmt,
              float* __restrict__ Ksum, __half* __restrict__ kvwt)
{
    const int bh = blockIdx.x;
    const int b = bh >> 3, h = bh & 7;
    const int tid = threadIdx.x;
    const int d = tid >> 5, v = tid & 31;
    __shared__ float Ks[32][33], Vs[32][33];
    __shared__ float Wms[256][33];

    float acc = 0.f, ks = 0.f;
    for (int s0 = 0; s0 < LTK; s0 += 32) {
        __syncthreads();
        const size_t gidx = (size_t)(b * LTK + s0 + d) * DD + h * DHH + v;
        Ks[d][v] = __half2float(Kf[gidx]);
        Vs[d][v] = __half2float(Vf[gidx]);
        __syncthreads();
        #pragma unroll
        for (int si = 0; si < 32; si++) {
            const float kk = Ks[si][d];
            acc = fmaf(kk, Vs[si][v], acc);
            ks += kk;
        }
    }
    if (v == 0) Ksum[bh * DHH + d] = ks;

    // stash KV tile and Wm slice in smem
    __syncthreads();
    Ks[d][v] = acc;                        // Ks[d][v] = KV[d][v]
    {
        const int n = tid >> 2, v0 = (tid & 3) * 8;
        const __half* wp = wmt + (size_t)n * 256 + h * DHH + v0;
        #pragma unroll
        for (int q = 0; q < 8; q++) Wms[n][v0 + q] = __half2float(wp[q]);
    }
    __syncthreads();

    // KVW[d][n] = sum_v KV[d][v] * wm[h*32+v][n]; thread: n = tid>>2, d-chunk
    {
        const int n = tid >> 2, dc = (tid & 3) * 8;
        float o[8] = {0.f, 0.f, 0.f, 0.f, 0.f, 0.f, 0.f, 0.f};
        #pragma unroll
        for (int vv = 0; vv < 32; vv++) {
            const float wv_ = Wms[n][vv];
            #pragma unroll
            for (int j = 0; j < 8; j++)
                o[j] = fmaf(Ks[dc + j][vv], wv_, o[j]);
        }
        __half2 hh[4];
        #pragma unroll
        for (int q = 0; q < 4; q++)
            hh[q] = __floats2half2_rn(o[2*q], o[2*q+1]);
        *(uint4*)(kvwt + (size_t)b * (DD*DD) + (size_t)n * DD + h * DHH + dc) =
            *(uint4*)hh;
    }
}

// ---------------------------------------------------------------------------
// qz: Qz = Q / (Q . Ksum + eps), per row; warp = head
// ---------------------------------------------------------------------------
__global__ void __launch_bounds__(256)
qz_kernel(const __half* __restrict__ Qf, const float* __restrict__ Ksum,
          __half* __restrict__ qz)
{
    const int row = blockIdx.x;
    const int b = row >> 9;
    const int tid = threadIdx.x;
    const int h = tid >> 5, v = tid & 31;

    const float q = __half2float(Qf[(size_t)row * DD + tid]);
    float qk = q * Ksum[(b * HH + h) * DHH + v];
    #pragma unroll
    for (int o = 16; o > 0; o >>= 1) qk += __shfl_xor_sync(0xffffffffu, qk, o);
    const float z = 1.f / (qk + ATT_EPS);
    qz[(size_t)row * DD + tid] = __float2half(q * z);
}

// ---------------------------------------------------------------------------
// LN1 (warp per row): half in, half out
// ---------------------------------------------------------------------------
__global__ void __launch_bounds__(256)
ln_y_kernel(const __half* __restrict__ x, const float* __restrict__ g,
            const float* __restrict__ bta, __half* __restrict__ y)
{
    const int row = blockIdx.x * 8 + (threadIdx.x >> 5);
    const int lane = threadIdx.x & 31;
    const __half2* xr = (const __half2*)(x + (size_t)row * DD);

    float v[8];
    #pragma unroll
    for (int q = 0; q < 4; q++) {
        const float2 f = __half22float2(xr[lane * 4 + q]);
        v[2*q] = f.x; v[2*q+1] = f.y;
    }
    float s = 0.f;
    #pragma unroll
    for (int q = 0; q < 8; q++) s += v[q];
    #pragma unroll
    for (int o = 16; o > 0; o >>= 1) s += __shfl_xor_sync(0xffffffffu, s, o);
    const float mean = s * (1.f / DD);
    float vs = 0.f;
    #pragma unroll
    for (int q = 0; q < 8; q++) { const float d = v[q] - mean; vs += d * d; }
    #pragma unroll
    for (int o = 16; o > 0; o >>= 1) vs += __shfl_xor_sync(0xffffffffu, vs, o);
    const float rstd = rsqrtf(vs * (1.f / DD) + LN_EPS);

    __half2* yr = (__half2*)(y + (size_t)row * DD);
    #pragma unroll
    for (int q = 0; q < 4; q++) {
        const int col = lane * 8 + 2 * q;
        const float y0 = (v[2*q]   - mean) * rstd * g[col]     + bta[col];
        const float y1 = (v[2*q+1] - mean) * rstd * g[col + 1] + bta[col + 1];
        yr[lane * 4 + q] = __floats2half2_rn(y0, y1);
    }
}

// ---------------------------------------------------------------------------
// LN2 + residual (warp per row): half in, fp32 out
// ---------------------------------------------------------------------------
__global__ void __launch_bounds__(256)
ln_res_kernel(const __half* __restrict__ x, const float* __restrict__ g,
              const float* __restrict__ bta, const float* __restrict__ sf,
              float* __restrict__ out)
{
    const int row = blockIdx.x * 8 + (threadIdx.x >> 5);
    const int lane = threadIdx.x & 31;
    const __half2* xr = (const __half2*)(x + (size_t)row * DD);

    float v[8];
    #pragma unroll
    for (int q = 0; q < 4; q++) {
        const float2 f = __half22float2(xr[lane * 4 + q]);
        v[2*q] = f.x; v[2*q+1] = f.y;
    }
    float s = 0.f;
    #pragma unroll
    for (int q = 0; q < 8; q++) s += v[q];
    #pragma unroll
    for (int o = 16; o > 0; o >>= 1) s += __shfl_xor_sync(0xffffffffu, s, o);
    const float mean = s * (1.f / DD);
    float vs = 0.f;
    #pragma unroll
    for (int q = 0; q < 8; q++) { const float d = v[q] - mean; vs += d * d; }
    #pragma unroll
    for (int o = 16; o > 0; o >>= 1) vs += __shfl_xor_sync(0xffffffffu, vs, o);
    const float rstd = rsqrtf(vs * (1.f / DD) + LN_EPS);

    const float* sfr = sf + (size_t)row * DD + lane * 8;
    float o0[8];
    const float4 s0 = *(const float4*)sfr;
    const float4 s1 = *(const float4*)(sfr + 4);
    const float* sp = &s0.x;
    #pragma unroll
    for (int q = 0; q < 4; q++) {
        const int col = lane * 8 + q;
        o0[q] = sp[q] + (v[q] - mean) * rstd * g[col] + bta[col];
    }
    const float* sp1 = &s1.x;
    #pragma unroll
    for (int q = 0; q < 4; q++) {
        const int col = lane * 8 + 4 + q;
        o0[4+q] = sp1[q] + (v[4+q] - mean) * rstd * g[col] + bta[col];
    }
    float* outr = out + (size_t)row * DD + lane * 8;
    *(float4*)outr = *(float4*)&o0[0];
    *(float4*)(outr + 4) = *(float4*)&o0[4];
}

// ---------------------------------------------------------------------------
// launch
// ---------------------------------------------------------------------------
extern "C" void kernel_launch(void* const* d_in, const int* in_sizes, int n_in,
                              void* d_out, int out_size)
{
    (void)in_sizes; (void)n_in; (void)out_size;
    const float* search_feat   = (const float*)d_in[0];
    const float* search_coors  = (const float*)d_in[1];
    const float* template_feat = (const float*)d_in[3];
    const float* pos_w1  = (const float*)d_in[6];
    const float* pos_b1  = (const float*)d_in[7];
    const float* pos_w2  = (const float*)d_in[8];
    const float* pos_b2  = (const float*)d_in[9];
    const float* wq      = (const float*)d_in[10];
    const float* wk      = (const float*)d_in[11];
    const float* wv      = (const float*)d_in[12];
    const float* w_merge = (const float*)d_in[13];
    const float* mlp_w1  = (const float*)d_in[14];
    const float* mlp_w2  = (const float*)d_in[15];
    const float* ln1_g   = (const float*)d_in[16];
    const float* ln1_b   = (const float*)d_in[17];
    const float* ln2_g   = (const float*)d_in[18];
    const float* ln2_b   = (const float*)d_in[19];
    float* out = (float*)d_out;

    __half *Qh, *Kh, *Vh, *qz, *kvwt, *msgm, *y, *mh, *m2h;
    float  *Ksum, *bq;
    __half *wkvt, *wmt, *w1t, *w2t, *qcombt;
    cudaGetSymbolAddress((void**)&Qh,   g_Qh);
    cudaGetSymbolAddress((void**)&Kh,   g_Kh);
    cudaGetSymbolAddress((void**)&Vh,   g_Vh);
    cudaGetSymbolAddress((void**)&Ksum, g_Ksum);
    cudaGetSymbolAddress((void**)&qz,   g_qz);
    cudaGetSymbolAddress((void**)&kvwt, g_kvwt);
    cudaGetSymbolAddress((void**)&msgm, g_msgm);
    cudaGetSymbolAddress((void**)&y,    g_y);
    cudaGetSymbolAddress((void**)&mh,   g_mh);
    cudaGetSymbolAddress((void**)&m2h,  g_m2h);
    cudaGetSymbolAddress((void**)&bq,   g_bq);
    cudaGetSymbolAddress((void**)&wkvt, g_wkvt);
    cudaGetSymbolAddress((void**)&wmt,  g_wmt);
    cudaGetSymbolAddress((void**)&w1t,  g_w1t);
    cudaGetSymbolAddress((void**)&w2t,  g_w2t);
    cudaGetSymbolAddress((void**)&qcombt, g_qcombt);

    cudaFuncSetAttribute(hgemm<EPI_ELU1B,1,2,0>, cudaFuncAttributeMaxDynamicSharedMemorySize, HG_SMEM);
    cudaFuncSetAttribute(hgemm<EPI_KV,1,3,0>,    cudaFuncAttributeMaxDynamicSharedMemorySize, HG_SMEM);
    cudaFuncSetAttribute(hgemm<EPI_NONE,1,0,1>,  cudaFuncAttributeMaxDynamicSharedMemorySize, HG_SMEM);
    cudaFuncSetAttribute(hgemm<EPI_RELU,1,4,0>,  cudaFuncAttributeMaxDynamicSharedMemorySize, HG_SMEM);
    cudaFuncSetAttribute(hgemm<EPI_NONE,1,0,0>,  cudaFuncAttributeMaxDynamicSharedMemorySize, HG_SMEM);

    const int MS = BB * LSQ;   // 32768
    const int MT = BB * LTK;   // 16384

    // prep (tiny)
    transpose_all<<<dim3(16, 16, 6), dim3(32, 32)>>>(
        wk, wv, w_merge, mlp_w1, mlp_w2, wq,
        wkvt, wmt, w1t, w2t, qcombt);
    wpq_kernel<<<256, 256>>>(pos_w2, wq, qcombt);
    bq_kernel<<<1, 256>>>(pos_b2, wq, bq);

    // 1) Q = elu([pos_hidden | sf] @ [Wpq; wq] + bq)+1  (pos MLP + f32 sf in loader)
    hgemm<EPI_ELU1B,1,2,0><<<dim3(2, MS/128), 256, HG_SMEM>>>(
        nullptr, search_feat, qcombt, Qh, nullptr, MS, DD, 2*DD,
        bq, search_coors, pos_w1, pos_b1);

    // 2) [K|V] = template_feat(fp32) @ [wk|wv]
    hgemm<EPI_KV,1,3,0><<<dim3(4, MT/128), 256, HG_SMEM>>>(
        nullptr, template_feat, wkvt, Kh, Vh, MT, 2*DD, DD,
        nullptr, nullptr, nullptr, nullptr);

    // 3) KV reduce + KVW fold (w_merge folded into attention)
    kv_kvw_kernel<<<BB * HH, 1024>>>(Kh, Vh, wmt, Ksum, kvwt);

    // 4) Qz = Q * z
    qz_kernel<<<MS, 256>>>(Qh, Ksum, qz);

    // 5) msgm = Qz @ KVWcat_b  (per-batch B)
    hgemm<EPI_NONE,1,0,1><<<dim3(2, MS/128), 256, HG_SMEM>>>(
        qz, nullptr, kvwt, msgm, nullptr, MS, DD, DD,
        nullptr, nullptr, nullptr, nullptr);

    // 6) y = ln1(msgm)
    ln_y_kernel<<<MS/8, 256>>>(msgm, ln1_g, ln1_b, y);

    // 7) mh = relu([sf(f32), y] @ mlp_w1)
    hgemm<EPI_RELU,1,4,0><<<dim3(4, MS/128), 256, HG_SMEM>>>(
        y, search_feat, w1t, mh, nullptr, MS, 2*DD, 2*DD,
        nullptr, nullptr, nullptr, nullptr);

    // 8) m2 = mh @ mlp_w2  (half out)
    hgemm<EPI_NONE,1,0,0><<<dim3(2, MS/128), 256, HG_SMEM>>>(
        mh, nullptr, w2t, m2h, nullptr, MS, DD, 2*DD,
        nullptr, nullptr, nullptr, nullptr);

    // 9) out = search_feat + ln2(m2)
    ln_res_kernel<<<MS/8, 256>>>(m2h, ln2_g, ln2_b, search_feat, out);
}

// round 12
// speedup vs baseline: 1.0901x; 1.0901x over previous
#include <cuda_runtime.h>
#include <cuda_fp16.h>
#include <math.h>
#include <stdint.h>

// Problem constants
#define BB  64
#define LSQ 512
#define LTK 256
#define DD  256
#define HH  8
#define DHH 32
#define LN_EPS  1e-5f
#define ATT_EPS 1e-6f

// ---------------------------------------------------------------------------
// Scratch (device globals)
// ---------------------------------------------------------------------------
__device__ __align__(16) __half g_sfh [BB*LSQ*DD];      // search_feat as half
__device__ __align__(16) __half g_Kh  [BB*LTK*DD];
__device__ __align__(16) __half g_Vh  [BB*LTK*DD];
__device__ float  g_Ksum[BB*HH*DHH];
__device__ __align__(16) __half g_qz  [BB*LSQ*DD];      // (elu(Q)+1) * z
__device__ __align__(16) __half g_kvwt[BB*DD*DD];       // per-b [n][k] = KVW
__device__ __align__(16) __half g_msgm[BB*LSQ*DD];
__device__ __align__(16) __half g_y   [BB*LSQ*DD];      // ln1 output
__device__ __align__(16) __half g_mh  [BB*LSQ*2*DD];
__device__ __align__(16) __half g_m2h [BB*LSQ*DD];
// weights, transposed to [N, K] in half
__device__ __align__(16) __half g_wkvt  [2*DD*DD];      // [wk ; wv]
__device__ __align__(16) __half g_wmt   [DD*DD];
__device__ __align__(16) __half g_w1t   [2*DD*2*DD];
__device__ __align__(16) __half g_w2t   [DD*2*DD];
__device__ __align__(16) __half g_qcombt[DD*2*DD];      // [Wpq ; wq] as [N=256][K=512]
__device__ float g_bq[DD];                               // pos_b2 @ wq

// ---------------------------------------------------------------------------
// helpers
// ---------------------------------------------------------------------------
__device__ __forceinline__ uint32_t smem_u32(const void* p) {
    uint32_t a;
    asm("{ .reg .u64 t; cvta.to.shared.u64 t, %1; cvt.u32.u64 %0, t; }"
        : "=r"(a) : "l"(p));
    return a;
}

__device__ __forceinline__ void cp_async16(uint32_t saddr, const void* gaddr) {
    asm volatile("cp.async.cg.shared.global [%0], [%1], 16;"
                 :: "r"(saddr), "l"(gaddr));
}
#define CP_COMMIT() asm volatile("cp.async.commit_group;" ::: "memory")
#define CP_WAIT(n)  asm volatile("cp.async.wait_group %0;" :: "n"(n) : "memory")

__device__ __forceinline__ void ldmx4(uint32_t r[4], uint32_t addr) {
    asm volatile("ldmatrix.sync.aligned.m8n8.x4.shared.b16 {%0,%1,%2,%3}, [%4];"
        : "=r"(r[0]), "=r"(r[1]), "=r"(r[2]), "=r"(r[3]) : "r"(addr));
}

__device__ __forceinline__ void mma16816(float d[4], const uint32_t a[4],
                                         uint32_t b0, uint32_t b1) {
    asm volatile(
        "mma.sync.aligned.m16n8k16.row.col.f32.f16.f16.f32 "
        "{%0,%1,%2,%3}, {%4,%5,%6,%7}, {%8,%9}, {%0,%1,%2,%3};"
        : "+f"(d[0]), "+f"(d[1]), "+f"(d[2]), "+f"(d[3])
        : "r"(a[0]), "r"(a[1]), "r"(a[2]), "r"(a[3]), "r"(b0), "r"(b1));
}

__device__ __forceinline__ void sts_h8(uint32_t addr, const __half2 h[4]) {
    asm volatile("st.shared.v4.b32 [%0], {%1,%2,%3,%4};"
        :: "r"(addr),
           "r"(*(const uint32_t*)&h[0]), "r"(*(const uint32_t*)&h[1]),
           "r"(*(const uint32_t*)&h[2]), "r"(*(const uint32_t*)&h[3])
        : "memory");
}

// ---------------------------------------------------------------------------
// fp16 GEMM, cp.async 3-stage, block 128x128x64, 8 warps (2x4), warp 64x32
// AMODE: 0 = half A [*,K]
//        1 = [A | A2] halves of K=512 (both half, cp.async)
//        2 = fused-Q: kcol<256 -> relu(coors@w1+b1) inline; kcol>=256 -> A2 half
//        3 = F fp32 [*,K] converted (blocking; small GEMMs only)
// EPI_QZ: elu(acc+bias)+1, then z = 1/(dot(head)+eps) via 2 shuffles, store v*z
// BATB: Bt += (m0>>9) * 65536 (per-batch B matrix)
// ---------------------------------------------------------------------------
enum { EPI_NONE = 0, EPI_QZ = 1, EPI_RELU = 3, EPI_KV = 4 };

#define ROWB 144
#define TILEB (128 * ROWB)             // 18432
#define STAGEB (2 * TILEB)             // 36864
#define NSTAGE 3
#define HG_SMEM (NSTAGE * STAGEB)      // 110592

template<int EPI, int HOUT, int AMODE, int BATB>
__global__ void __launch_bounds__(256)
hgemm(const __half* __restrict__ A, const __half* __restrict__ A2,
      const float* __restrict__ F,
      const __half* __restrict__ Bt,
      void* __restrict__ Cv, void* __restrict__ C2,
      int M, int N, int K,
      const float* __restrict__ bias, const float* __restrict__ ksum,
      const float* __restrict__ coors, const float* __restrict__ w1p,
      const float* __restrict__ b1p)
{
    extern __shared__ __align__(16) char smem[];
    const uint32_t sb = smem_u32(smem);
    const int tid = threadIdx.x, lane = tid & 31, wid = tid >> 5;
    const int wm = (wid & 1) * 64, wn = (wid >> 1) * 32;
    const int m0 = blockIdx.y * 128, n0 = blockIdx.x * 128;
    const int nk = K >> 6;
    const __half* Btb = BATB ? (Bt + (size_t)(m0 >> 9) * (DD * DD)) : Bt;

    float acc[4][4][4];
    #pragma unroll
    for (int a = 0; a < 4; a++)
        #pragma unroll
        for (int b = 0; b < 4; b++)
            #pragma unroll
            for (int c = 0; c < 4; c++) acc[a][b][c] = 0.f;

    auto issue_stage = [&](int s, int ktile) {
        const uint32_t abase = sb + s * STAGEB;
        const uint32_t bbase = abase + TILEB;
        #pragma unroll
        for (int i = 0; i < 4; i++) {
            const int idx = tid + i * 256;            // 0..1023
            const int row = idx >> 3, c8 = idx & 7;
            const int kcol = ktile * 64 + c8 * 8;
            const uint32_t sad = abase + row * ROWB + c8 * 16;
            if (AMODE == 2) {
                if (kcol < 256) {
                    const int m = m0 + row;
                    const float c0 = coors[m*3+0], c1 = coors[m*3+1],
                                c2 = coors[m*3+2];
                    __half2 h[4];
                    #pragma unroll
                    for (int q = 0; q < 4; q++) {
                        const int n = kcol + 2 * q;
                        float x0 = b1p[n]   + c0*w1p[n]   + c1*w1p[256+n]
                                 + c2*w1p[512+n];
                        float x1 = b1p[n+1] + c0*w1p[n+1] + c1*w1p[256+n+1]
                                 + c2*w1p[512+n+1];
                        h[q] = __floats2half2_rn(fmaxf(x0, 0.f), fmaxf(x1, 0.f));
                    }
                    sts_h8(sad, h);
                } else {
                    cp_async16(sad, A2 + (size_t)(m0 + row) * 256 + (kcol - 256));
                }
            } else if (AMODE == 1) {
                const __half* asrc = (kcol < 256)
                    ? (A  + (size_t)(m0 + row) * 256 + kcol)
                    : (A2 + (size_t)(m0 + row) * 256 + (kcol - 256));
                cp_async16(sad, asrc);
            } else if (AMODE == 3) {
                const float* fp = F + (size_t)(m0 + row) * K + kcol;
                const float4 f0 = *(const float4*)fp;
                const float4 f1 = *(const float4*)(fp + 4);
                __half2 h[4] = { __floats2half2_rn(f0.x, f0.y),
                                 __floats2half2_rn(f0.z, f0.w),
                                 __floats2half2_rn(f1.x, f1.y),
                                 __floats2half2_rn(f1.z, f1.w) };
                sts_h8(sad, h);
            } else {
                cp_async16(sad, A + (size_t)(m0 + row) * K + kcol);
            }
            cp_async16(bbase + row * ROWB + c8 * 16,
                       Btb + (size_t)(n0 + row) * K + kcol);
        }
        CP_COMMIT();
    };

    #pragma unroll
    for (int s = 0; s < NSTAGE - 1; s++) issue_stage(s, s);

    const int lr = lane & 15, lc = (lane >> 4) * 8;

    for (int kt = 0; kt < nk; kt++) {
        CP_WAIT(NSTAGE - 2);
        __syncthreads();
        const int st = kt % NSTAGE;
        if (kt + NSTAGE - 1 < nk)
            issue_stage((kt + NSTAGE - 1) % NSTAGE, kt + NSTAGE - 1);

        const uint32_t abuf = sb + st * STAGEB;
        const uint32_t bbuf = abuf + TILEB;
        #pragma unroll
        for (int ks = 0; ks < 4; ks++) {
            uint32_t afr[4][4], bfr[2][4];
            #pragma unroll
            for (int mi = 0; mi < 4; mi++)
                ldmx4(afr[mi], abuf + (wm + mi * 16 + lr) * ROWB + (ks * 16 + lc) * 2);
            #pragma unroll
            for (int nj = 0; nj < 2; nj++)
                ldmx4(bfr[nj], bbuf + (wn + nj * 16 + lr) * ROWB + (ks * 16 + lc) * 2);
            #pragma unroll
            for (int mi = 0; mi < 4; mi++)
                #pragma unroll
                for (int ni = 0; ni < 4; ni++) {
                    const int nj = ni >> 1;
                    const uint32_t b0 = (ni & 1) ? bfr[nj][1] : bfr[nj][0];
                    const uint32_t b1 = (ni & 1) ? bfr[nj][3] : bfr[nj][2];
                    mma16816(acc[mi][ni], afr[mi], b0, b1);
                }
        }
    }

    if (EPI == EPI_QZ) {
        // warp's 32-col tile == one head. z computed in-epilogue.
        const int h = (n0 + wn) >> 5;
        const int bh32 = ((m0 >> 9) * HH + h) * DHH;
        float ksv[8];
        #pragma unroll
        for (int ni = 0; ni < 4; ni++) {
            const int d = ni * 8 + (lane & 3) * 2;
            ksv[ni*2]   = ksum[bh32 + d];
            ksv[ni*2+1] = ksum[bh32 + d + 1];
        }
        #pragma unroll
        for (int mi = 0; mi < 4; mi++) {
            #pragma unroll
            for (int half_m = 0; half_m < 2; half_m++) {
                const int m = m0 + wm + mi * 16 + (lane >> 2) + half_m * 8;
                float v[8];
                float qk = 0.f;
                #pragma unroll
                for (int ni = 0; ni < 4; ni++) {
                    const int col = n0 + wn + ni * 8 + (lane & 3) * 2;
                    float v0 = acc[mi][ni][half_m * 2 + 0] + bias[col];
                    float v1 = acc[mi][ni][half_m * 2 + 1] + bias[col + 1];
                    v0 = v0 > 0.f ? v0 + 1.f : expf(v0);
                    v1 = v1 > 0.f ? v1 + 1.f : expf(v1);
                    v[ni*2] = v0; v[ni*2+1] = v1;
                    qk = fmaf(v0, ksv[ni*2], qk);
                    qk = fmaf(v1, ksv[ni*2+1], qk);
                }
                qk += __shfl_xor_sync(0xffffffffu, qk, 1);
                qk += __shfl_xor_sync(0xffffffffu, qk, 2);
                const float z = 1.f / (qk + ATT_EPS);
                #pragma unroll
                for (int ni = 0; ni < 4; ni++) {
                    const int col = n0 + wn + ni * 8 + (lane & 3) * 2;
                    *(__half2*)((__half*)Cv + (size_t)m * N + col) =
                        __floats2half2_rn(v[ni*2] * z, v[ni*2+1] * z);
                }
            }
        }
        return;
    }

    // generic epilogue
    #pragma unroll
    for (int mi = 0; mi < 4; mi++) {
        #pragma unroll
        for (int ni = 0; ni < 4; ni++) {
            const int col = n0 + wn + ni * 8 + (lane & 3) * 2;
            #pragma unroll
            for (int half_m = 0; half_m < 2; half_m++) {
                const int m = m0 + wm + mi * 16 + (lane >> 2) + half_m * 8;
                float v0 = acc[mi][ni][half_m * 2 + 0];
                float v1 = acc[mi][ni][half_m * 2 + 1];
                if (EPI == EPI_RELU) {
                    v0 = fmaxf(v0, 0.f);
                    v1 = fmaxf(v1, 0.f);
                }
                if (EPI == EPI_KV) {
                    if (col < 256) {
                        v0 = v0 > 0.f ? v0 + 1.f : expf(v0);
                        v1 = v1 > 0.f ? v1 + 1.f : expf(v1);
                        *(__half2*)((__half*)Cv + (size_t)m * 256 + col) =
                            __floats2half2_rn(v0, v1);
                    } else {
                        *(__half2*)((__half*)C2 + (size_t)m * 256 + (col - 256)) =
                            __floats2half2_rn(v0, v1);
                    }
                } else if (HOUT) {
                    *(__half2*)((__half*)Cv + (size_t)m * N + col) = __floats2half2_rn(v0, v1);
                } else {
                    *(float2*)((float*)Cv + (size_t)m * N + col) = make_float2(v0, v1);
                }
            }
        }
    }
}

// ---------------------------------------------------------------------------
// batched weight transpose -> half (into [N][K] layouts)
// ---------------------------------------------------------------------------
__global__ void transpose_all(const float* __restrict__ wk, const float* __restrict__ wv,
                              const float* __restrict__ wm, const float* __restrict__ w1,
                              const float* __restrict__ w2, const float* __restrict__ wq,
                              __half* __restrict__ wkvt, __half* __restrict__ wmt,
                              __half* __restrict__ w1t, __half* __restrict__ w2t,
                              __half* __restrict__ qcombt)
{
    __shared__ float t[32][33];
    const int z = blockIdx.z;
    const float* W; __half* Wt; int Kd, Nd, Ks_out, roff = 0, coff = 0;
    switch (z) {
        case 0: W = wk; Wt = wkvt;  Kd = 256; Nd = 256; Ks_out = 256; break;
        case 1: W = wv; Wt = wkvt;  Kd = 256; Nd = 256; Ks_out = 256; roff = 256; break;
        case 2: W = wm; Wt = wmt;   Kd = 256; Nd = 256; Ks_out = 256; break;
        case 3: W = w1; Wt = w1t;   Kd = 512; Nd = 512; Ks_out = 512; break;
        case 4: W = w2; Wt = w2t;   Kd = 512; Nd = 256; Ks_out = 512; break;
        default: W = wq; Wt = qcombt; Kd = 256; Nd = 256; Ks_out = 512; coff = 256; break;
    }
    const int k0 = blockIdx.y * 32, n0 = blockIdx.x * 32;
    if (k0 >= Kd || n0 >= Nd) return;
    t[threadIdx.y][threadIdx.x] = W[(size_t)(k0 + threadIdx.y) * Nd + n0 + threadIdx.x];
    __syncthreads();
    Wt[(size_t)(roff + n0 + threadIdx.y) * Ks_out + coff + k0 + threadIdx.x] =
        __float2half(t[threadIdx.x][threadIdx.y]);
}

// Wpq[k][n] = (posw2 @ wq)[k][n] -> qcombt[n][k] (k < 256)
__global__ void __launch_bounds__(256)
wpq_kernel(const float* __restrict__ posw2, const float* __restrict__ wq,
           __half* __restrict__ qcombt)
{
    __shared__ float srow[256];
    const int k = blockIdx.x, n = threadIdx.x;
    srow[n] = posw2[(size_t)k * 256 + n];
    __syncthreads();
    float acc = 0.f;
    #pragma unroll 8
    for (int j = 0; j < 256; j++)
        acc = fmaf(srow[j], wq[(size_t)j * 256 + n], acc);
    qcombt[(size_t)n * 512 + k] = __float2half(acc);
}

// bq[n] = (pos_b2 @ wq)[n]
__global__ void __launch_bounds__(256)
bq_kernel(const float* __restrict__ pb2, const float* __restrict__ wq,
          float* __restrict__ bq)
{
    const int n = threadIdx.x;
    float acc = 0.f;
    for (int j = 0; j < 256; j++)
        acc = fmaf(pb2[j], wq[(size_t)j * 256 + n], acc);
    bq[n] = acc;
}

// fp32 -> fp16, 8 elems/thread
__global__ void f2h_kernel(const float* __restrict__ in, __half* __restrict__ out, int n)
{
    const int base = (blockIdx.x * blockDim.x + threadIdx.x) * 8;
    if (base >= n) return;
    const float4 a = *(const float4*)(in + base);
    const float4 b = *(const float4*)(in + base + 4);
    __half2 h[4] = { __floats2half2_rn(a.x, a.y), __floats2half2_rn(a.z, a.w),
                     __floats2half2_rn(b.x, b.y), __floats2half2_rn(b.z, b.w) };
    *(uint4*)(out + base) = *(uint4*)h;
}

// ---------------------------------------------------------------------------
// KV reduce + KVW = KV @ Wm_h, per (b,h); writes Ksum and kvwt[b][n][h*32+d]
// ---------------------------------------------------------------------------
__global__ void __launch_bounds__(1024)
kv_kvw_kernel(const __half* __restrict__ Kf, const __half* __restrict__ Vf,
              const __half* __restrict__ wmt,
              float* __restrict__ Ksum, __half* __restrict__ kvwt)
{
    const int bh = blockIdx.x;
    const int b = bh >> 3, h = bh & 7;
    const int tid = threadIdx.x;
    const int d = tid >> 5, v = tid & 31;
    __shared__ float Ks[32][33], Vs[32][33];
    __shared__ float Wms[256][33];

    float acc = 0.f, ks = 0.f;
    for (int s0 = 0; s0 < LTK; s0 += 32) {
        __syncthreads();
        const size_t gidx = (size_t)(b * LTK + s0 + d) * DD + h * DHH + v;
        Ks[d][v] = __half2float(Kf[gidx]);
        Vs[d][v] = __half2float(Vf[gidx]);
        __syncthreads();
        #pragma unroll
        for (int si = 0; si < 32; si++) {
            const float kk = Ks[si][d];
            acc = fmaf(kk, Vs[si][v], acc);
            ks += kk;
        }
    }
    if (v == 0) Ksum[bh * DHH + d] = ks;

    __syncthreads();
    Ks[d][v] = acc;                        // Ks[d][v] = KV[d][v]
    {
        const int n = tid >> 2, v0 = (tid & 3) * 8;
        const __half* wp = wmt + (size_t)n * 256 + h * DHH + v0;
        #pragma unroll
        for (int q = 0; q < 8; q++) Wms[n][v0 + q] = __half2float(wp[q]);
    }
    __syncthreads();

    {
        const int n = tid >> 2, dc = (tid & 3) * 8;
        float o[8] = {0.f, 0.f, 0.f, 0.f, 0.f, 0.f, 0.f, 0.f};
        #pragma unroll
        for (int vv = 0; vv < 32; vv++) {
            const float wv_ = Wms[n][vv];
            #pragma unroll
            for (int j = 0; j < 8; j++)
                o[j] = fmaf(Ks[dc + j][vv], wv_, o[j]);
        }
        __half2 hh[4];
        #pragma unroll
        for (int q = 0; q < 4; q++)
            hh[q] = __floats2half2_rn(o[2*q], o[2*q+1]);
        *(uint4*)(kvwt + (size_t)b * (DD*DD) + (size_t)n * DD + h * DHH + dc) =
            *(uint4*)hh;
    }
}

// ---------------------------------------------------------------------------
// LN1 (warp per row): half in, half out
// ---------------------------------------------------------------------------
__global__ void __launch_bounds__(256)
ln_y_kernel(const __half* __restrict__ x, const float* __restrict__ g,
            const float* __restrict__ bta, __half* __restrict__ y)
{
    const int row = blockIdx.x * 8 + (threadIdx.x >> 5);
    const int lane = threadIdx.x & 31;
    const __half2* xr = (const __half2*)(x + (size_t)row * DD);

    float v[8];
    #pragma unroll
    for (int q = 0; q < 4; q++) {
        const float2 f = __half22float2(xr[lane * 4 + q]);
        v[2*q] = f.x; v[2*q+1] = f.y;
    }
    float s = 0.f;
    #pragma unroll
    for (int q = 0; q < 8; q++) s += v[q];
    #pragma unroll
    for (int o = 16; o > 0; o >>= 1) s += __shfl_xor_sync(0xffffffffu, s, o);
    const float mean = s * (1.f / DD);
    float vs = 0.f;
    #pragma unroll
    for (int q = 0; q < 8; q++) { const float d = v[q] - mean; vs += d * d; }
    #pragma unroll
    for (int o = 16; o > 0; o >>= 1) vs += __shfl_xor_sync(0xffffffffu, vs, o);
    const float rstd = rsqrtf(vs * (1.f / DD) + LN_EPS);

    __half2* yr = (__half2*)(y + (size_t)row * DD);
    #pragma unroll
    for (int q = 0; q < 4; q++) {
        const int col = lane * 8 + 2 * q;
        const float y0 = (v[2*q]   - mean) * rstd * g[col]     + bta[col];
        const float y1 = (v[2*q+1] - mean) * rstd * g[col + 1] + bta[col + 1];
        yr[lane * 4 + q] = __floats2half2_rn(y0, y1);
    }
}

// ---------------------------------------------------------------------------
// LN2 + residual (warp per row): half in, fp32 out
// ---------------------------------------------------------------------------
__global__ void __launch_bounds__(256)
ln_res_kernel(const __half* __restrict__ x, const float* __restrict__ g,
              const float* __restrict__ bta, const float* __restrict__ sf,
              float* __restrict__ out)
{
    const int row = blockIdx.x * 8 + (threadIdx.x >> 5);
    const int lane = threadIdx.x & 31;
    const __half2* xr = (const __half2*)(x + (size_t)row * DD);

    float v[8];
    #pragma unroll
    for (int q = 0; q < 4; q++) {
        const float2 f = __half22float2(xr[lane * 4 + q]);
        v[2*q] = f.x; v[2*q+1] = f.y;
    }
    float s = 0.f;
    #pragma unroll
    for (int q = 0; q < 8; q++) s += v[q];
    #pragma unroll
    for (int o = 16; o > 0; o >>= 1) s += __shfl_xor_sync(0xffffffffu, s, o);
    const float mean = s * (1.f / DD);
    float vs = 0.f;
    #pragma unroll
    for (int q = 0; q < 8; q++) { const float d = v[q] - mean; vs += d * d; }
    #pragma unroll
    for (int o = 16; o > 0; o >>= 1) vs += __shfl_xor_sync(0xffffffffu, vs, o);
    const float rstd = rsqrtf(vs * (1.f / DD) + LN_EPS);

    const float* sfr = sf + (size_t)row * DD + lane * 8;
    float o0[8];
    const float4 s0 = *(const float4*)sfr;
    const float4 s1 = *(const float4*)(sfr + 4);
    const float* sp = &s0.x;
    #pragma unroll
    for (int q = 0; q < 4; q++) {
        const int col = lane * 8 + q;
        o0[q] = sp[q] + (v[q] - mean) * rstd * g[col] + bta[col];
    }
    const float* sp1 = &s1.x;
    #pragma unroll
    for (int q = 0; q < 4; q++) {
        const int col = lane * 8 + 4 + q;
        o0[4+q] = sp1[q] + (v[4+q] - mean) * rstd * g[col] + bta[col];
    }
    float* outr = out + (size_t)row * DD + lane * 8;
    *(float4*)outr = *(float4*)&o0[0];
    *(float4*)(outr + 4) = *(float4*)&o0[4];
}

// ---------------------------------------------------------------------------
// launch
// ---------------------------------------------------------------------------
extern "C" void kernel_launch(void* const* d_in, const int* in_sizes, int n_in,
                              void* d_out, int out_size)
{
    (void)in_sizes; (void)n_in; (void)out_size;
    const float* search_feat   = (const float*)d_in[0];
    const float* search_coors  = (const float*)d_in[1];
    const float* template_feat = (const float*)d_in[3];
    const float* pos_w1  = (const float*)d_in[6];
    const float* pos_b1  = (const float*)d_in[7];
    const float* pos_w2  = (const float*)d_in[8];
    const float* pos_b2  = (const float*)d_in[9];
    const float* wq      = (const float*)d_in[10];
    const float* wk      = (const float*)d_in[11];
    const float* wv      = (const float*)d_in[12];
    const float* w_merge = (const float*)d_in[13];
    const float* mlp_w1  = (const float*)d_in[14];
    const float* mlp_w2  = (const float*)d_in[15];
    const float* ln1_g   = (const float*)d_in[16];
    const float* ln1_b   = (const float*)d_in[17];
    const float* ln2_g   = (const float*)d_in[18];
    const float* ln2_b   = (const float*)d_in[19];
    float* out = (float*)d_out;

    __half *sfh, *Kh, *Vh, *qz, *kvwt, *msgm, *y, *mh, *m2h;
    float  *Ksum, *bq;
    __half *wkvt, *wmt, *w1t, *w2t, *qcombt;
    cudaGetSymbolAddress((void**)&sfh,  g_sfh);
    cudaGetSymbolAddress((void**)&Kh,   g_Kh);
    cudaGetSymbolAddress((void**)&Vh,   g_Vh);
    cudaGetSymbolAddress((void**)&Ksum, g_Ksum);
    cudaGetSymbolAddress((void**)&qz,   g_qz);
    cudaGetSymbolAddress((void**)&kvwt, g_kvwt);
    cudaGetSymbolAddress((void**)&msgm, g_msgm);
    cudaGetSymbolAddress((void**)&y,    g_y);
    cudaGetSymbolAddress((void**)&mh,   g_mh);
    cudaGetSymbolAddress((void**)&m2h,  g_m2h);
    cudaGetSymbolAddress((void**)&bq,   g_bq);
    cudaGetSymbolAddress((void**)&wkvt, g_wkvt);
    cudaGetSymbolAddress((void**)&wmt,  g_wmt);
    cudaGetSymbolAddress((void**)&w1t,  g_w1t);
    cudaGetSymbolAddress((void**)&w2t,  g_w2t);
    cudaGetSymbolAddress((void**)&qcombt, g_qcombt);

    cudaFuncSetAttribute(hgemm<EPI_KV,1,3,0>,   cudaFuncAttributeMaxDynamicSharedMemorySize, HG_SMEM);
    cudaFuncSetAttribute(hgemm<EPI_QZ,1,2,0>,   cudaFuncAttributeMaxDynamicSharedMemorySize, HG_SMEM);
    cudaFuncSetAttribute(hgemm<EPI_NONE,1,0,1>, cudaFuncAttributeMaxDynamicSharedMemorySize, HG_SMEM);
    cudaFuncSetAttribute(hgemm<EPI_RELU,1,1,0>, cudaFuncAttributeMaxDynamicSharedMemorySize, HG_SMEM);
    cudaFuncSetAttribute(hgemm<EPI_NONE,1,0,0>, cudaFuncAttributeMaxDynamicSharedMemorySize, HG_SMEM);

    const int MS = BB * LSQ;   // 32768
    const int MT = BB * LTK;   // 16384

    // prep (tiny)
    transpose_all<<<dim3(16, 16, 6), dim3(32, 32)>>>(
        wk, wv, w_merge, mlp_w1, mlp_w2, wq,
        wkvt, wmt, w1t, w2t, qcombt);
    wpq_kernel<<<256, 256>>>(pos_w2, wq, qcombt);
    bq_kernel<<<1, 256>>>(pos_b2, wq, bq);
    f2h_kernel<<<(MS*DD)/(256*8), 256>>>(search_feat, sfh, MS*DD);

    // 1) [K|V] = template_feat(fp32) @ [wk|wv]
    hgemm<EPI_KV,1,3,0><<<dim3(4, MT/128), 256, HG_SMEM>>>(
        nullptr, nullptr, template_feat, wkvt, Kh, Vh, MT, 2*DD, DD,
        nullptr, nullptr, nullptr, nullptr, nullptr);

    // 2) KV reduce + KVW fold (w_merge folded into attention)
    kv_kvw_kernel<<<BB * HH, 1024>>>(Kh, Vh, wmt, Ksum, kvwt);

    // 3) qz = (elu([pos_hidden | sfh] @ [Wpq; wq] + bq)+1) * z   (qz fused in epilogue)
    hgemm<EPI_QZ,1,2,0><<<dim3(2, MS/128), 256, HG_SMEM>>>(
        nullptr, sfh, nullptr, qcombt, qz, nullptr, MS, DD, 2*DD,
        bq, Ksum, search_coors, pos_w1, pos_b1);

    // 4) msgm = qz @ KVWcat_b  (per-batch B)
    hgemm<EPI_NONE,1,0,1><<<dim3(2, MS/128), 256, HG_SMEM>>>(
        qz, nullptr, nullptr, kvwt, msgm, nullptr, MS, DD, DD,
        nullptr, nullptr, nullptr, nullptr, nullptr);

    // 5) y = ln1(msgm)
    ln_y_kernel<<<MS/8, 256>>>(msgm, ln1_g, ln1_b, y);

    // 6) mh = relu([sfh, y] @ mlp_w1)  (dual half A, cp.async)
    hgemm<EPI_RELU,1,1,0><<<dim3(4, MS/128), 256, HG_SMEM>>>(
        sfh, y, nullptr, w1t, mh, nullptr, MS, 2*DD, 2*DD,
        nullptr, nullptr, nullptr, nullptr, nullptr);

    // 7) m2 = mh @ mlp_w2  (half out)
    hgemm<EPI_NONE,1,0,0><<<dim3(2, MS/128), 256, HG_SMEM>>>(
        mh, nullptr, nullptr, w2t, m2h, nullptr, MS, DD, 2*DD,
        nullptr, nullptr, nullptr, nullptr, nullptr);

    // 8) out = search_feat + ln2(m2)
    ln_res_kernel<<<MS/8, 256>>>(m2h, ln2_g, ln2_b, search_feat, out);
}